// round 4
// baseline (speedup 1.0000x reference)
#include <cuda_runtime.h>
#include <math.h>

#define BATCH   64
#define NLIST   512
#define THREADS 512
#define NBLK    128            // 2 blocks per row (offset-split)

#define LOG_EPS (-23.025850929940457f)
#define LN2F    0.6931471805599453f

__device__ float        g_partial[NBLK];
__device__ unsigned int g_count = 0;

__global__ __launch_bounds__(THREADS)
void rank_loss_main(const float* __restrict__ logits,
                    const float* __restrict__ labels,
                    float* __restrict__ out) {
    __shared__ float  s_sl[NLIST];          // masked logits (rank phase, broadcast reads)
    __shared__ float4 sA[NLIST + 256];      // {Gj, Ej, hj, labj(NaN if invalid)} + mirror
    __shared__ float  sBp[NLIST + 256];     // qd with capped packed in low 8 mantissa bits
    __shared__ float  s_invlog[52];
    __shared__ float  s_rel[52 * 32];       // replicated: [cd*32 + lane] -> conflict-free
    __shared__ float  s_red[16];
    __shared__ bool   s_last;

    const int tid   = threadIdx.x;
    const int lane  = tid & 31;
    const int b     = blockIdx.x >> 1;
    const int jhalf = blockIdx.x & 1;

    // --- LUT setup ---
    if (tid < 52) s_invlog[tid] = tid ? (1.0f / log1pf((float)tid)) : 0.0f;
    for (int idx = tid; idx < 52 * 32; idx += THREADS) {
        int rd = idx >> 5;
        s_rel[idx] = rd ? 0.75f * fabsf(1.0f / log1pf((float)rd)
                                      - 1.0f / log1pf((float)(rd + 1)))
                        : 0.0f;
    }

    // --- per-element load / masking ---
    const float g_raw   = logits[b * NLIST + tid];
    const float lab_raw = labels[b * NLIST + tid];
    const bool  valid   = lab_raw > -1000.0f;
    const float lab     = valid ? lab_raw : 0.0f;
    const float g       = valid ? g_raw : LOG_EPS;
    s_sl[tid] = g;
    __syncthreads();

    // --- rank = 1 + #{slj > sli}; ties only among invalid cluster (capped=51, disc=0
    //     either way, and those elements appear only in masked pairs) -> exact ---
    int cnt = 0;
    const float4* sl4 = (const float4*)s_sl;
    #pragma unroll 8
    for (int j4 = 0; j4 < NLIST / 4; ++j4) {
        float4 v = sl4[j4];
        cnt += (v.x > g);
        cnt += (v.y > g);
        cnt += (v.z > g);
        cnt += (v.w > g);
    }
    const int   rank   = cnt + 1;
    const int   capped = min(rank, 51);
    const float disc   = (rank <= 50) ? s_invlog[rank] : 0.0f;

    // --- per-element precompute ---
    const float Gi   = __expf(0.5f * g);     // exp(logit/2)
    const float Ei   = __expf(0.5f * lab);   // exp(label/2)
    const float hi   = 0.5f * g;
    const float nhi  = -hi;
    const float qdi  = 0.25f * disc;
    const float qnan = __int_as_float(0x7fffffff);
    const float labi = valid ? lab : qnan;   // NaN: |diff|>0 false -> pair inactive

    // pack capped into low 8 mantissa bits of qd (rel perturbation < 2^-15)
    const unsigned qbits = (__float_as_uint(qdi) & ~0xFFu) | (unsigned)capped;
    const float4 Av = make_float4(Gi, Ei, hi, labi);
    sA[tid]  = Av;
    sBp[tid] = __uint_as_float(qbits);
    if (tid < 256) { sA[NLIST + tid] = Av; sBp[NLIST + tid] = __uint_as_float(qbits); }
    __syncthreads();

    // --- per-row IDCG (thread 0; first 50 positions, validity via NaN sentinel) ---
    float idcg = 0.0f;
    if (tid == 0) {
        float s = 0.0f;
        #pragma unroll
        for (int p = 1; p <= 50; ++p)
            if (sA[p - 1].w < 1e30f) s += s_invlog[p];   // NaN -> false
        idcg = (s > 0.0f) ? (1.0f / s) : 0.0f;
    }

    // --- unordered-pair loop. Orientation-free identity:
    //     bce = ln2*lg2(Gi+Gj) - hi + dh*Ej/(Ei+Ej)   (same for BOTH orientations)
    //     mask: |labi-labj| > 0 (NaN-safe). Each unordered pair hit exactly once. ---
    const float* relbase = s_rel + lane;
    const int    o0      = 1 + (jhalf << 7);
    const float4* pA = sA  + tid + o0;
    const float*  pB = sBp + tid + o0;

    float acc = 0.0f;
    #pragma unroll 16
    for (int oo = 0; oo < 127; ++oo) {
        const float4 A   = pA[oo];
        const float  Bp  = pB[oo];
        const float  S   = Ei + A.y;
        const float  t2  = __fdividef(A.y, S);            // Ej / (Ei+Ej)
        const float  lg  = __log2f(Gi + A.x);
        const float  dh  = hi - A.z;
        const float  core = fmaf(lg, LN2F, nhi);
        const float  bce  = fmaf(dh, t2, core);
        const float  dl   = labi - A.w;                   // NaN if either invalid
        const int    cj   = (int)(__float_as_uint(Bp) & 0xFFu);
        const int    cd   = abs(capped - cj);
        float w = relbase[cd << 5] + fabsf(qdi - Bp);
        w = (fabsf(dl) > 0.0f) ? w : 0.0f;
        acc = fmaf(bce, w, acc);
    }
    {   // final offset (o0+127 == 128 or 256); offset 256 double-covered -> gate
        const float4 A   = pA[127];
        const float  Bp  = pB[127];
        const bool   gate = (jhalf == 0) | (tid < 256);
        const float  S   = Ei + A.y;
        const float  t2  = __fdividef(A.y, S);
        const float  lg  = __log2f(Gi + A.x);
        const float  dh  = hi - A.z;
        const float  core = fmaf(lg, LN2F, nhi);
        const float  bce  = fmaf(dh, t2, core);
        const float  dl   = labi - A.w;
        const int    cj   = (int)(__float_as_uint(Bp) & 0xFFu);
        const int    cd   = abs(capped - cj);
        float w = relbase[cd << 5] + fabsf(qdi - Bp);
        w = (gate && fabsf(dl) > 0.0f) ? w : 0.0f;
        acc = fmaf(bce, w, acc);
    }

    // --- deterministic block reduce + fused final reduce ---
    #pragma unroll
    for (int o = 16; o; o >>= 1) acc += __shfl_down_sync(0xffffffffu, acc, o);
    if (lane == 0) s_red[tid >> 5] = acc;
    __syncthreads();
    if (tid < 16) {
        float v = s_red[tid];
        #pragma unroll
        for (int o = 8; o; o >>= 1) v += __shfl_down_sync(0xffffu, v, o);
        if (tid == 0) {
            g_partial[blockIdx.x] = v * idcg * (1.0f / (float)BATCH);
            __threadfence();
            unsigned int old = atomicInc(&g_count, NBLK - 1);  // wraps -> replay-safe
            s_last = (old == NBLK - 1);
        }
    }
    __syncthreads();

    if (s_last) {
        __threadfence();
        if (tid < NBLK) {
            float v = ((volatile float*)g_partial)[tid];
            #pragma unroll
            for (int o = 16; o; o >>= 1) v += __shfl_down_sync(0xffffffffu, v, o);
            if (lane == 0) s_red[tid >> 5] = v;
        }
        __syncthreads();
        if (tid == 0) {
            float tot = 0.0f;
            #pragma unroll
            for (int w2 = 0; w2 < NBLK / 32; ++w2) tot += s_red[w2];
            out[0] = tot;
        }
    }
}

extern "C" void kernel_launch(void* const* d_in, const int* in_sizes, int n_in,
                              void* d_out, int out_size) {
    const float* logits = (const float*)d_in[0];
    const float* labels = (const float*)d_in[1];
    float* out = (float*)d_out;
    (void)in_sizes; (void)n_in; (void)out_size;

    rank_loss_main<<<NBLK, THREADS>>>(logits, labels, out);
}